// round 13
// baseline (speedup 1.0000x reference)
#include <cuda_runtime.h>
#include <cuda_bf16.h>
#include <cuda_fp16.h>
#include <cstdint>

#define NN 100000
#define NE 1600000
#define DD 128
#define NG 128
#define NB 196              // scan blocks: 196*512 >= NN
#define TLCNT 1563          // (NN+63)/64 tiles of 64 rows
#define TL3 391             // (NN+255)/256 tiles of 256 rows
#define HISTB 3125          // NE/512
#define XCONVB 3125         // NN*DD/4096

// ---------------- scratch (static device globals; zero-initialized) ---------
__device__ __align__(16) float g_h[NN * DD];        // final fp32 activations
__device__ __align__(16) __half g_xh[NN * DD];      // fp16 copy of input x
__device__ __align__(16) __half g_hh0[NN * DD];     // fp16 activations (layer0 out)
__device__ __align__(16) __half g_hh1[NN * DD];     // fp16 activations (layer1 out)
__device__ int g_deg[NN];
__device__ int g_rowptr[NN + 1];
__device__ int g_cursor[NN];
__device__ int g_esorted[NE];
__device__ unsigned long long g_desc[NB];
// aggregated tiles: single fp16 plane, swizzled MMA layout.
// (TLCNT+1)*64 = 100096 rows = exactly TL3*256 — pad rows stay zero.
__device__ __align__(16) __half g_a16[(TLCNT + 1) * 8192];
// pre-transposed, pre-swizzled fp16 hi/lo weights {W1_0,W2_0,W1_1,W2_1,W1_2,W2_2}
__device__ __align__(16) __half g_whi[6][16384];
__device__ __align__(16) __half g_wlo[6][16384];

__device__ __forceinline__ __half2 U2H(unsigned u) {
    return *reinterpret_cast<__half2*>(&u);
}

// ---------------- inline index-width detection ------------------------------
__device__ __forceinline__ int detect64(const void* p) {
    const unsigned* w = (const unsigned*)p;
    unsigned acc = 0;
    #pragma unroll
    for (int i = 0; i < 16; i++) acc |= w[2 * i + 1];
    return acc == 0u;
}

// ---------------- launch 0: weight prep + degree hist + x->fp16 -------------
__device__ __forceinline__ uint32_t w_off(int n, int k) {
    return (uint32_t)(n * 128 + (((k >> 3) ^ (n & 7)) << 3) + (k & 7));
}

__global__ void __launch_bounds__(512) pre_kernel(
        const void* __restrict__ ei, const float* __restrict__ x,
        const float* w0, const float* w1, const float* w2,
        const float* w3, const float* w4, const float* w5) {
    if (blockIdx.x < 6) {
        const float* src[6] = {w0, w1, w2, w3, w4, w5};
        const float* W = src[blockIdx.x];
        for (int i = threadIdx.x; i < 16384; i += 512) {
            int k = i >> 7, n = i & 127;
            float v = W[i];
            __half hi = __float2half_rn(v);
            __half lo = __float2half_rn(v - __half2float(hi));
            uint32_t idx = w_off(n, k);
            g_whi[blockIdx.x][idx] = hi;
            g_wlo[blockIdx.x][idx] = lo;
        }
        return;
    }
    if (blockIdx.x >= 6 + HISTB) {
        int base = (blockIdx.x - 6 - HISTB) * 4096 + threadIdx.x * 8;
        float4 a = __ldg((const float4*)(x + base));
        float4 b = __ldg((const float4*)(x + base + 4));
        __half2 p0 = __floats2half2_rn(a.x, a.y);
        __half2 p1 = __floats2half2_rn(a.z, a.w);
        __half2 p2 = __floats2half2_rn(b.x, b.y);
        __half2 p3 = __floats2half2_rn(b.z, b.w);
        uint4 u;
        u.x = reinterpret_cast<uint32_t&>(p0);
        u.y = reinterpret_cast<uint32_t&>(p1);
        u.z = reinterpret_cast<uint32_t&>(p2);
        u.w = reinterpret_cast<uint32_t&>(p3);
        *reinterpret_cast<uint4*>(g_xh + base) = u;
        return;
    }
    __shared__ int s_is64;
    if (threadIdx.x == 0) s_is64 = detect64(ei);
    __syncthreads();
    int e = (blockIdx.x - 6) * 512 + threadIdx.x;   // grid exact
    int dst = s_is64 ? (int)((const long long*)ei)[(long)NE + e]
                     : ((const int*)ei)[NE + e];
    atomicAdd(&g_deg[dst], 1);
}

// ---------------- launch 1: single-kernel exclusive scan ---------------------
__global__ void __launch_bounds__(512) scan_kernel() {
    int b = blockIdx.x, t = threadIdx.x;
    int idx = b * 512 + t;
    int v = (idx < NN) ? g_deg[idx] : 0;
    int lane = t & 31, w = t >> 5;
    int x = v;
    #pragma unroll
    for (int o = 1; o < 32; o <<= 1) {
        int u = __shfl_up_sync(~0u, x, o);
        if (lane >= o) x += u;
    }
    __shared__ int ws[16], wo[16];
    __shared__ int s_prefix, s_total;
    if (lane == 31) ws[w] = x;
    __syncthreads();
    if (t < 16) {
        int y = ws[t], z = y;
        #pragma unroll
        for (int o = 1; o < 16; o <<= 1) {
            int u = __shfl_up_sync(0xffffu, z, o, 16);
            if (t >= o) z += u;
        }
        wo[t] = z - y;
        if (t == 15) s_total = z;
    }
    __syncthreads();
    int incl = x + wo[w];
    if (t == 0)
        atomicExch(&g_desc[b], (1ULL << 32) | (unsigned)s_total);   // AGGREGATE
    if (t < 32) {
        long long running = 0;
        int i = b - 1 - t;
        while (true) {
            unsigned long long d = (2ULL << 32);
            if (i >= 0) {
                do { d = atomicAdd(&g_desc[i], 0ULL); } while ((d >> 32) == 0ULL);
            }
            int isPre = ((d >> 32) == 2ULL);
            unsigned pm = __ballot_sync(~0u, isPre);
            if (pm) {
                int fp = __ffs(pm) - 1;
                long long val = (t <= fp) ? (long long)(unsigned)d : 0;
                #pragma unroll
                for (int o = 16; o; o >>= 1) val += __shfl_down_sync(~0u, val, o);
                running += __shfl_sync(~0u, val, 0);
                break;
            } else {
                long long val = (long long)(unsigned)d;
                #pragma unroll
                for (int o = 16; o; o >>= 1) val += __shfl_down_sync(~0u, val, o);
                running += __shfl_sync(~0u, val, 0);
                i -= 32;
            }
        }
        if (t == 0) {
            s_prefix = (int)running;
            atomicExch(&g_desc[b],
                       (2ULL << 32) | (unsigned)(running + s_total));   // PREFIX
        }
    }
    __syncthreads();
    int excl = s_prefix + incl - v;
    if (idx < NN) { g_rowptr[idx] = excl; g_cursor[idx] = excl; }
    if (idx == NN - 1) g_rowptr[NN] = s_prefix + incl;
}

// ---------------- launch 2: CSR fill ----------------------------------------
__global__ void __launch_bounds__(512) fill_kernel(const void* __restrict__ ei) {
    __shared__ int s_is64;
    if (threadIdx.x == 0) s_is64 = detect64(ei);
    __syncthreads();
    int e = blockIdx.x * 512 + threadIdx.x;   // grid exact
    int dst, src;
    if (s_is64) {
        dst = (int)((const long long*)ei)[(long)NE + e];
        src = (int)((const long long*)ei)[e];
    } else {
        dst = ((const int*)ei)[NE + e];
        src = ((const int*)ei)[e];
    }
    int pos = atomicAdd(&g_cursor[dst], 1);
    g_esorted[pos] = src;
}

// ---------------- aggregation: warp-per-node, fp16 tree accumulation --------
__global__ void __launch_bounds__(256) agg_kernel(const __half* __restrict__ hin) {
    int gw = (blockIdx.x * 256 + threadIdx.x) >> 5;   // node index
    if (gw >= NN) return;
    int lane = threadIdx.x & 31;
    const uint2* h2 = (const uint2*)hin;
    const int* es = g_esorted;

    float4 acc;
    {
        uint2 u = __ldg(&h2[gw * 32 + lane]);
        float2 a = __half22float2(U2H(u.x));
        float2 b = __half22float2(U2H(u.y));
        acc = make_float4(a.x, a.y, b.x, b.y);
    }
    int j = g_rowptr[gw], e = g_rowptr[gw + 1];

    int i0, i1, i2, i3, i4, i5, i6, i7;
    bool have = (j + 8 <= e);
    if (have) {
        i0 = __ldg(&es[j]);     i1 = __ldg(&es[j + 1]);
        i2 = __ldg(&es[j + 2]); i3 = __ldg(&es[j + 3]);
        i4 = __ldg(&es[j + 4]); i5 = __ldg(&es[j + 5]);
        i6 = __ldg(&es[j + 6]); i7 = __ldg(&es[j + 7]);
    }
    #pragma unroll 1
    while (have) {
        uint2 uu[8];
        uu[0] = __ldg(&h2[i0 * 32 + lane]);
        uu[1] = __ldg(&h2[i1 * 32 + lane]);
        uu[2] = __ldg(&h2[i2 * 32 + lane]);
        uu[3] = __ldg(&h2[i3 * 32 + lane]);
        uu[4] = __ldg(&h2[i4 * 32 + lane]);
        uu[5] = __ldg(&h2[i5 * 32 + lane]);
        uu[6] = __ldg(&h2[i6 * 32 + lane]);
        uu[7] = __ldg(&h2[i7 * 32 + lane]);
        bool nxt = (j + 16 <= e);
        int x0, x1, x2, x3, x4, x5, x6, x7;
        if (nxt) {
            x0 = __ldg(&es[j + 8]);  x1 = __ldg(&es[j + 9]);
            x2 = __ldg(&es[j + 10]); x3 = __ldg(&es[j + 11]);
            x4 = __ldg(&es[j + 12]); x5 = __ldg(&es[j + 13]);
            x6 = __ldg(&es[j + 14]); x7 = __ldg(&es[j + 15]);
        }
        __half2 sx = __hadd2(__hadd2(__hadd2(U2H(uu[0].x), U2H(uu[1].x)),
                                     __hadd2(U2H(uu[2].x), U2H(uu[3].x))),
                             __hadd2(__hadd2(U2H(uu[4].x), U2H(uu[5].x)),
                                     __hadd2(U2H(uu[6].x), U2H(uu[7].x))));
        __half2 sy = __hadd2(__hadd2(__hadd2(U2H(uu[0].y), U2H(uu[1].y)),
                                     __hadd2(U2H(uu[2].y), U2H(uu[3].y))),
                             __hadd2(__hadd2(U2H(uu[4].y), U2H(uu[5].y)),
                                     __hadd2(U2H(uu[6].y), U2H(uu[7].y))));
        float2 f0 = __half22float2(sx);
        float2 f1 = __half22float2(sy);
        acc.x += f0.x; acc.y += f0.y; acc.z += f1.x; acc.w += f1.y;
        j += 8;
        if (nxt) { i0 = x0; i1 = x1; i2 = x2; i3 = x3;
                   i4 = x4; i5 = x5; i6 = x6; i7 = x7; }
        have = nxt;
    }
    for (; j < e; j++) {
        int s = __ldg(&es[j]);
        uint2 u = __ldg(&h2[s * 32 + lane]);
        float2 a = __half22float2(U2H(u.x));
        float2 b = __half22float2(U2H(u.y));
        acc.x += a.x; acc.y += a.y; acc.z += b.x; acc.w += b.y;
    }

    int tile = gw >> 6, row = gw & 63;
    int col = lane * 4;
    uint32_t off = (uint32_t)(tile * 16384 + row * 256
                              + (((col >> 3) ^ (row & 7)) << 4) + (col & 7) * 2);
    __half2 p0 = __floats2half2_rn(acc.x, acc.y);
    __half2 p1 = __floats2half2_rn(acc.z, acc.w);
    uint2 u;
    u.x = reinterpret_cast<uint32_t&>(p0);
    u.y = reinterpret_cast<uint32_t&>(p1);
    *reinterpret_cast<uint2*>(reinterpret_cast<char*>(g_a16) + off) = u;
}

// ---------------- warp-MMA helpers ------------------------------------------
__device__ __forceinline__ uint32_t smem_u32(const void* p) {
    uint32_t a;
    asm("{ .reg .u64 t; cvta.to.shared.u64 t, %1; cvt.u32.u64 %0, t; }"
        : "=r"(a) : "l"(p));
    return a;
}
__device__ __forceinline__ void ldsm4(unsigned r[4], uint32_t addr) {
    asm volatile("ldmatrix.sync.aligned.m8n8.x4.shared.b16 {%0,%1,%2,%3}, [%4];"
                 : "=r"(r[0]), "=r"(r[1]), "=r"(r[2]), "=r"(r[3]) : "r"(addr));
}
__device__ __forceinline__ void mma16816(float c[4], const unsigned a[4],
                                         const unsigned b[2]) {
    asm volatile(
        "mma.sync.aligned.m16n8k16.row.col.f32.f16.f16.f32 "
        "{%0,%1,%2,%3}, {%4,%5,%6,%7}, {%8,%9}, {%0,%1,%2,%3};"
        : "+f"(c[0]), "+f"(c[1]), "+f"(c[2]), "+f"(c[3])
        : "r"(a[0]), "r"(a[1]), "r"(a[2]), "r"(a[3]), "r"(b[0]), "r"(b[1]));
}
__device__ __forceinline__ void cpa16(uint32_t saddr, const void* gaddr) {
    asm volatile("cp.async.ca.shared.global [%0], [%1], 16;"
                 :: "r"(saddr), "l"(gaddr) : "memory");
}

// 256x128 @ 128x128 stage; warp = 64 rows x 32 cols (4 m-tiles x 4 n-tiles)
__device__ __forceinline__ void mma_stage(uint32_t aP,
                                          uint32_t wHi, uint32_t wLo,
                                          int mq, int nq, int lane,
                                          float c[4][4][4]) {
    #pragma unroll
    for (int mt = 0; mt < 4; mt++)
        #pragma unroll
        for (int nt = 0; nt < 4; nt++)
            #pragma unroll
            for (int q = 0; q < 4; q++) c[mt][nt][q] = 0.f;

    int m = lane >> 3, r = lane & 7;
    uint32_t aRow[4], bRow[2];
    #pragma unroll
    for (int mt = 0; mt < 4; mt++)
        aRow[mt] = (uint32_t)(mq * 64 + mt * 16 + (m & 1) * 8 + r) * 256;
    #pragma unroll
    for (int bt = 0; bt < 2; bt++)
        bRow[bt] = (uint32_t)(nq * 32 + bt * 16 + (m >> 1) * 8 + r) * 256;
    int aAdd = m >> 1, bAdd = m & 1;

    #pragma unroll
    for (int k = 0; k < 8; k++) {
        unsigned a[4][4], bh[2][4], bl[2][4];
        uint32_t ac = (uint32_t)(((k * 2 + aAdd) ^ r) << 4);
        uint32_t bc = (uint32_t)(((k * 2 + bAdd) ^ r) << 4);
        #pragma unroll
        for (int mt = 0; mt < 4; mt++)
            ldsm4(a[mt], aP + aRow[mt] + ac);
        #pragma unroll
        for (int bt = 0; bt < 2; bt++) {
            ldsm4(bh[bt], wHi + bRow[bt] + bc);
            ldsm4(bl[bt], wLo + bRow[bt] + bc);
        }
        #pragma unroll
        for (int mt = 0; mt < 4; mt++)
            #pragma unroll
            for (int nt = 0; nt < 4; nt++) {
                const unsigned* BH = bh[nt >> 1] + (nt & 1) * 2;
                const unsigned* BL = bl[nt >> 1] + (nt & 1) * 2;
                mma16816(c[mt][nt], a[mt], BH);
                mma16816(c[mt][nt], a[mt], BL);
            }
    }
}

__device__ __forceinline__ void store_h16(char* pA, int row, int col,
                                          float f0, float f1) {
    __half2 h = __floats2half2_rn(f0, f1);
    uint32_t off = (uint32_t)(row * 256 + (((col >> 3) ^ (row & 7)) << 4)
                              + (col & 7) * 2);
    *(__half2*)(pA + off) = h;
}

__device__ __forceinline__ void stcs2(float* p, float v0, float v1) {
    asm volatile("st.global.cs.v2.f32 [%0], {%1,%2};" :: "l"(p), "f"(v0), "f"(v1)
                 : "memory");
}
__device__ __forceinline__ void stcsh2(__half* p, float v0, float v1) {
    __half2 h = __floats2half2_rn(v0, v1);
    unsigned u = reinterpret_cast<unsigned&>(h);
    asm volatile("st.global.cs.u32 [%0], %1;" :: "l"(p), "r"(u) : "memory");
}

// ---------------- persistent MMA kernel --------------------------------------
// 148 CTAs (1/SM), 512 threads, 192KB smem: W1+W2 hi/lo staged ONCE; loop over
// 256-row tiles, A (64KB) loaded via cp.async per tile.
__global__ void __launch_bounds__(512, 1) mma_kernel(
        const float* __restrict__ b1, const float* __restrict__ b2,
        float* __restrict__ hout32, __half* __restrict__ hout16,
        int widx, int relu2) {
    extern __shared__ char smem[];
    char* pW1h = smem;              // 32KB each plane
    char* pW1l = smem + 32768;
    char* pW2h = smem + 65536;
    char* pW2l = smem + 98304;
    char* pA   = smem + 131072;     // 64KB (256 rows x 256B)

    int tid = threadIdx.x;
    int lane = tid & 31, wid = tid >> 5;

    // ---- stage all weights once (linear copies; pre-swizzled) ----
    {
        const float4* s1h = (const float4*)g_whi[widx];
        const float4* s1l = (const float4*)g_wlo[widx];
        const float4* s2h = (const float4*)g_whi[widx + 1];
        const float4* s2l = (const float4*)g_wlo[widx + 1];
        #pragma unroll
        for (int i = 0; i < 4; i++) {
            int j = tid + 512 * i;
            ((float4*)pW1h)[j] = s1h[j];
            ((float4*)pW1l)[j] = s1l[j];
            ((float4*)pW2h)[j] = s2h[j];
            ((float4*)pW2l)[j] = s2l[j];
        }
    }

    uint32_t aP  = smem_u32(pA);
    uint32_t w1h = smem_u32(pW1h), w1l = smem_u32(pW1l);
    uint32_t w2h = smem_u32(pW2h), w2l = smem_u32(pW2l);
    int mq = wid & 3;
    int nq = wid >> 2;
    int gid = lane >> 2, lc = (lane & 3) * 2;

    #pragma unroll 1
    for (int t = blockIdx.x; t < TL3; t += gridDim.x) {
        // load this tile's A (64KB): 512 threads x 128B
        {
            uint32_t dst = aP + (uint32_t)tid * 128;
            const char* src = (const char*)g_a16 + (size_t)t * 65536 + tid * 128;
            #pragma unroll
            for (int i = 0; i < 8; i++) cpa16(dst + i * 16, src + i * 16);
            asm volatile("cp.async.commit_group;" ::: "memory");
            asm volatile("cp.async.wait_group 0;" ::: "memory");
        }
        __syncthreads();

        int nodeBase = t * 256;
        float c[4][4][4];
        mma_stage(aP, w1h, w1l, mq, nq, lane, c);
        __syncthreads();   // all reads of A done before epi1 overwrites

        // ---- epilogue 1: relu(C+b1) -> fp16 back into A buffer ----
        #pragma unroll
        for (int mt = 0; mt < 4; mt++)
            #pragma unroll
            for (int nt = 0; nt < 4; nt++) {
                int col = nq * 32 + nt * 8 + lc;
                float2 bb = *(const float2*)&b1[col];
                int r0 = mq * 64 + mt * 16 + gid;
                float f0 = fmaxf(c[mt][nt][0] + bb.x, 0.f);
                float f1 = fmaxf(c[mt][nt][1] + bb.y, 0.f);
                float f2 = fmaxf(c[mt][nt][2] + bb.x, 0.f);
                float f3 = fmaxf(c[mt][nt][3] + bb.y, 0.f);
                store_h16(pA, r0,     col, f0, f1);
                store_h16(pA, r0 + 8, col, f2, f3);
            }
        __syncthreads();

        mma_stage(aP, w2h, w2l, mq, nq, lane, c);

        // ---- epilogue 2: C + b2 (+relu) -> gmem ----
        #pragma unroll
        for (int mt = 0; mt < 4; mt++)
            #pragma unroll
            for (int nt = 0; nt < 4; nt++) {
                int col = nq * 32 + nt * 8 + lc;
                float2 bb = *(const float2*)&b2[col];
                float v0 = c[mt][nt][0] + bb.x;
                float v1 = c[mt][nt][1] + bb.y;
                float v2 = c[mt][nt][2] + bb.x;
                float v3 = c[mt][nt][3] + bb.y;
                if (relu2) {
                    v0 = fmaxf(v0, 0.f); v1 = fmaxf(v1, 0.f);
                    v2 = fmaxf(v2, 0.f); v3 = fmaxf(v3, 0.f);
                }
                int r0 = mq * 64 + mt * 16 + gid;
                int n0 = nodeBase + r0;
                int n1 = n0 + 8;
                if (relu2) {
                    if (n0 < NN) stcsh2(&hout16[n0 * DD + col], v0, v1);
                    if (n1 < NN) stcsh2(&hout16[n1 * DD + col], v2, v3);
                } else {
                    if (n0 < NN) stcs2(&hout32[n0 * DD + col], v0, v1);
                    if (n1 < NN) stcs2(&hout32[n1 * DD + col], v2, v3);
                }
            }
        __syncthreads();   // stage2 A reads done before next tile's load
    }
}

// ---------------- mean pool over sorted batch + cleanup ----------------------
__device__ __forceinline__ int lbound_batch(const void* b, int val, int is64) {
    int lo = 0, hi = NN;
    if (is64) {
        const long long* p = (const long long*)b;
        long long v = val;
        while (lo < hi) { int mid = (lo + hi) >> 1; if (p[mid] < v) lo = mid + 1; else hi = mid; }
    } else {
        const int* p = (const int*)b;
        while (lo < hi) { int mid = (lo + hi) >> 1; if (p[mid] < val) lo = mid + 1; else hi = mid; }
    }
    return lo;
}

__global__ void pool_kernel(const float* __restrict__ h,
                            const void* __restrict__ batch,
                            const void* __restrict__ ei,
                            float* __restrict__ out) {
    {
        int gtid = blockIdx.x * 512 + threadIdx.x;   // 65536 threads
        g_deg[gtid] = 0;
        int g2 = gtid + 65536;
        if (g2 < NN) g_deg[g2] = 0;
        if (gtid < NB) g_desc[gtid] = 0ULL;
    }
    __shared__ int s_is64;
    if (threadIdx.x == 0) s_is64 = detect64(ei);
    __syncthreads();
    int g = blockIdx.x;
    int d = threadIdx.x & 127;
    int sub = threadIdx.x >> 7;
    int start = lbound_batch(batch, g, s_is64);
    int end   = lbound_batch(batch, g + 1, s_is64);
    float acc = 0.f;
    for (int n = start + sub; n < end; n += 4)
        acc += h[n * DD + d];
    __shared__ float red[512];
    red[threadIdx.x] = acc;
    __syncthreads();
    if (sub == 0) {
        float s = (red[d] + red[d + 128]) + (red[d + 256] + red[d + 384]);
        int cnt = end - start;
        out[g * DD + d] = s / (float)(cnt > 0 ? cnt : 1);
    }
}

// ---------------- launch ------------------------------------------------------
extern "C" void kernel_launch(void* const* d_in, const int* in_sizes, int n_in,
                              void* d_out, int out_size) {
    const float* x = (const float*)d_in[0];
    const void* ei = d_in[1];
    const void* batch = d_in[2];
    const float *W1[3], *b1[3], *W2[3], *b2[3];
    for (int l = 0; l < 3; l++) {
        W1[l] = (const float*)d_in[3 + 4 * l];
        b1[l] = (const float*)d_in[4 + 4 * l];
        W2[l] = (const float*)d_in[5 + 4 * l];
        b2[l] = (const float*)d_in[6 + 4 * l];
    }
    float* out = (float*)d_out;

    cudaFuncSetAttribute(mma_kernel,
                         cudaFuncAttributeMaxDynamicSharedMemorySize, 196608);

    float* h;
    __half *xh, *hh0, *hh1;
    cudaGetSymbolAddress((void**)&h, g_h);
    cudaGetSymbolAddress((void**)&xh, g_xh);
    cudaGetSymbolAddress((void**)&hh0, g_hh0);
    cudaGetSymbolAddress((void**)&hh1, g_hh1);

    const int agg_blocks = (NN * 32 + 255) / 256;   // 12500

    pre_kernel<<<6 + HISTB + XCONVB, 512>>>(ei, x, W1[0], W2[0], W1[1], W2[1],
                                            W1[2], W2[2]);                       // 0
    scan_kernel<<<NB, 512>>>();                                                   // 1
    fill_kernel<<<NE / 512, 512>>>(ei);                                           // 2

    agg_kernel<<<agg_blocks, 256>>>(xh);                                          // 3 (profiled)
    mma_kernel<<<148, 512, 196608>>>(b1[0], b2[0], nullptr, hh0, 0, 1);           // 4
    agg_kernel<<<agg_blocks, 256>>>(hh0);                                         // 5
    mma_kernel<<<148, 512, 196608>>>(b1[1], b2[1], nullptr, hh1, 2, 1);           // 6
    agg_kernel<<<agg_blocks, 256>>>(hh1);                                         // 7
    mma_kernel<<<148, 512, 196608>>>(b1[2], b2[2], h, nullptr, 4, 0);             // 8

    pool_kernel<<<NG, 512>>>(h, batch, ei, out);                                  // 9
}

// round 14
// speedup vs baseline: 1.0102x; 1.0102x over previous
#include <cuda_runtime.h>
#include <cuda_bf16.h>
#include <cuda_fp16.h>
#include <cstdint>

#define NN 100000
#define NE 1600000
#define DD 128
#define NG 128
#define NB 196              // scan blocks: 196*512 >= NN
#define TLCNT 1563          // (NN+63)/64 tiles of 64 rows
#define HISTB 3125          // NE/512
#define XCONVB 3125         // NN*DD/4096

// ---------------- scratch (static device globals; zero-initialized) ---------
__device__ __align__(16) float g_h[NN * DD];        // final fp32 activations
__device__ __align__(16) __half g_xh[NN * DD];      // fp16 copy of input x
__device__ __align__(16) __half g_hh0[NN * DD];     // fp16 activations (layer0 out)
__device__ __align__(16) __half g_hh1[NN * DD];     // fp16 activations (layer1 out)
__device__ int g_deg[NN];
__device__ int g_rowptr[NN + 1];
__device__ int g_cursor[NN];
__device__ __align__(16) int g_esorted[NE];
__device__ unsigned long long g_desc[NB];
// aggregated tiles: single fp16 plane, swizzled MMA layout (+1 pad tile)
__device__ __align__(16) __half g_a16[(TLCNT + 1) * 8192];
// pre-transposed, pre-swizzled fp16 hi/lo weights {W1_0,W2_0,W1_1,W2_1,W1_2,W2_2}
__device__ __align__(16) __half g_whi[6][16384];
__device__ __align__(16) __half g_wlo[6][16384];

__device__ __forceinline__ __half2 U2H(unsigned u) {
    return *reinterpret_cast<__half2*>(&u);
}

// ---------------- inline index-width detection ------------------------------
__device__ __forceinline__ int detect64(const void* p) {
    const unsigned* w = (const unsigned*)p;
    unsigned acc = 0;
    #pragma unroll
    for (int i = 0; i < 16; i++) acc |= w[2 * i + 1];
    return acc == 0u;
}

// ---------------- launch 0: weight prep + degree hist + x->fp16 -------------
__device__ __forceinline__ uint32_t w_off(int n, int k) {
    return (uint32_t)(n * 128 + (((k >> 3) ^ (n & 7)) << 3) + (k & 7));
}

__global__ void __launch_bounds__(512) pre_kernel(
        const void* __restrict__ ei, const float* __restrict__ x,
        const float* w0, const float* w1, const float* w2,
        const float* w3, const float* w4, const float* w5) {
    if (blockIdx.x < 6) {
        const float* src[6] = {w0, w1, w2, w3, w4, w5};
        const float* W = src[blockIdx.x];
        for (int i = threadIdx.x; i < 16384; i += 512) {
            int k = i >> 7, n = i & 127;
            float v = W[i];
            __half hi = __float2half_rn(v);
            __half lo = __float2half_rn(v - __half2float(hi));
            uint32_t idx = w_off(n, k);
            g_whi[blockIdx.x][idx] = hi;
            g_wlo[blockIdx.x][idx] = lo;
        }
        return;
    }
    if (blockIdx.x >= 6 + HISTB) {
        int base = (blockIdx.x - 6 - HISTB) * 4096 + threadIdx.x * 8;
        float4 a = __ldg((const float4*)(x + base));
        float4 b = __ldg((const float4*)(x + base + 4));
        __half2 p0 = __floats2half2_rn(a.x, a.y);
        __half2 p1 = __floats2half2_rn(a.z, a.w);
        __half2 p2 = __floats2half2_rn(b.x, b.y);
        __half2 p3 = __floats2half2_rn(b.z, b.w);
        uint4 u;
        u.x = reinterpret_cast<uint32_t&>(p0);
        u.y = reinterpret_cast<uint32_t&>(p1);
        u.z = reinterpret_cast<uint32_t&>(p2);
        u.w = reinterpret_cast<uint32_t&>(p3);
        *reinterpret_cast<uint4*>(g_xh + base) = u;
        return;
    }
    __shared__ int s_is64;
    if (threadIdx.x == 0) s_is64 = detect64(ei);
    __syncthreads();
    int e = (blockIdx.x - 6) * 512 + threadIdx.x;   // grid exact
    int dst = s_is64 ? (int)((const long long*)ei)[(long)NE + e]
                     : ((const int*)ei)[NE + e];
    atomicAdd(&g_deg[dst], 1);
}

// ---------------- launch 1: single-kernel exclusive scan ---------------------
__global__ void __launch_bounds__(512) scan_kernel() {
    int b = blockIdx.x, t = threadIdx.x;
    int idx = b * 512 + t;
    int v = (idx < NN) ? g_deg[idx] : 0;
    int lane = t & 31, w = t >> 5;
    int x = v;
    #pragma unroll
    for (int o = 1; o < 32; o <<= 1) {
        int u = __shfl_up_sync(~0u, x, o);
        if (lane >= o) x += u;
    }
    __shared__ int ws[16], wo[16];
    __shared__ int s_prefix, s_total;
    if (lane == 31) ws[w] = x;
    __syncthreads();
    if (t < 16) {
        int y = ws[t], z = y;
        #pragma unroll
        for (int o = 1; o < 16; o <<= 1) {
            int u = __shfl_up_sync(0xffffu, z, o, 16);
            if (t >= o) z += u;
        }
        wo[t] = z - y;
        if (t == 15) s_total = z;
    }
    __syncthreads();
    int incl = x + wo[w];
    if (t == 0)
        atomicExch(&g_desc[b], (1ULL << 32) | (unsigned)s_total);   // AGGREGATE
    if (t < 32) {
        long long running = 0;
        int i = b - 1 - t;
        while (true) {
            unsigned long long d = (2ULL << 32);
            if (i >= 0) {
                do { d = atomicAdd(&g_desc[i], 0ULL); } while ((d >> 32) == 0ULL);
            }
            int isPre = ((d >> 32) == 2ULL);
            unsigned pm = __ballot_sync(~0u, isPre);
            if (pm) {
                int fp = __ffs(pm) - 1;
                long long val = (t <= fp) ? (long long)(unsigned)d : 0;
                #pragma unroll
                for (int o = 16; o; o >>= 1) val += __shfl_down_sync(~0u, val, o);
                running += __shfl_sync(~0u, val, 0);
                break;
            } else {
                long long val = (long long)(unsigned)d;
                #pragma unroll
                for (int o = 16; o; o >>= 1) val += __shfl_down_sync(~0u, val, o);
                running += __shfl_sync(~0u, val, 0);
                i -= 32;
            }
        }
        if (t == 0) {
            s_prefix = (int)running;
            atomicExch(&g_desc[b],
                       (2ULL << 32) | (unsigned)(running + s_total));   // PREFIX
        }
    }
    __syncthreads();
    int excl = s_prefix + incl - v;
    if (idx < NN) { g_rowptr[idx] = excl; g_cursor[idx] = excl; }
    if (idx == NN - 1) g_rowptr[NN] = s_prefix + incl;
}

// ---------------- launch 2: CSR fill ----------------------------------------
__global__ void __launch_bounds__(512) fill_kernel(const void* __restrict__ ei) {
    __shared__ int s_is64;
    if (threadIdx.x == 0) s_is64 = detect64(ei);
    __syncthreads();
    int e = blockIdx.x * 512 + threadIdx.x;   // grid exact
    int dst, src;
    if (s_is64) {
        dst = (int)((const long long*)ei)[(long)NE + e];
        src = (int)((const long long*)ei)[e];
    } else {
        dst = ((const int*)ei)[NE + e];
        src = ((const int*)ei)[e];
    }
    int pos = atomicAdd(&g_cursor[dst], 1);
    g_esorted[pos] = src;
}

// ---------------- aggregation: warp-per-node, vectorized index loads --------
__global__ void __launch_bounds__(256) agg_kernel(const __half* __restrict__ hin) {
    int gw = (blockIdx.x * 256 + threadIdx.x) >> 5;   // node index
    if (gw >= NN) return;
    int lane = threadIdx.x & 31;
    const uint2* h2 = (const uint2*)hin;
    const int* es = g_esorted;

    float4 acc;
    {
        uint2 u = __ldg(&h2[gw * 32 + lane]);
        float2 a = __half22float2(U2H(u.x));
        float2 b = __half22float2(U2H(u.y));
        acc = make_float4(a.x, a.y, b.x, b.y);
    }
    int j = g_rowptr[gw], e = g_rowptr[gw + 1];

    // head-peel to 16B alignment of &es[j]
    while (j < e && (j & 3)) {
        int s = __ldg(&es[j++]);
        uint2 u = __ldg(&h2[s * 32 + lane]);
        float2 a = __half22float2(U2H(u.x));
        float2 b = __half22float2(U2H(u.y));
        acc.x += a.x; acc.y += a.y; acc.z += b.x; acc.w += b.y;
    }

    int4 A0, A1;   // 8 prefetched indices (two LDG.128)
    bool have = (j + 8 <= e);
    if (have) {
        A0 = __ldg((const int4*)&es[j]);
        A1 = __ldg((const int4*)&es[j + 4]);
    }
    #pragma unroll 1
    while (have) {
        uint2 uu[8];
        uu[0] = __ldg(&h2[A0.x * 32 + lane]);
        uu[1] = __ldg(&h2[A0.y * 32 + lane]);
        uu[2] = __ldg(&h2[A0.z * 32 + lane]);
        uu[3] = __ldg(&h2[A0.w * 32 + lane]);
        uu[4] = __ldg(&h2[A1.x * 32 + lane]);
        uu[5] = __ldg(&h2[A1.y * 32 + lane]);
        uu[6] = __ldg(&h2[A1.z * 32 + lane]);
        uu[7] = __ldg(&h2[A1.w * 32 + lane]);
        bool nxt = (j + 16 <= e);
        int4 B0, B1;
        if (nxt) {
            B0 = __ldg((const int4*)&es[j + 8]);
            B1 = __ldg((const int4*)&es[j + 12]);
        }
        // fp16 tree sum of 8 edges (error pooled away downstream)
        __half2 sx = __hadd2(__hadd2(__hadd2(U2H(uu[0].x), U2H(uu[1].x)),
                                     __hadd2(U2H(uu[2].x), U2H(uu[3].x))),
                             __hadd2(__hadd2(U2H(uu[4].x), U2H(uu[5].x)),
                                     __hadd2(U2H(uu[6].x), U2H(uu[7].x))));
        __half2 sy = __hadd2(__hadd2(__hadd2(U2H(uu[0].y), U2H(uu[1].y)),
                                     __hadd2(U2H(uu[2].y), U2H(uu[3].y))),
                             __hadd2(__hadd2(U2H(uu[4].y), U2H(uu[5].y)),
                                     __hadd2(U2H(uu[6].y), U2H(uu[7].y))));
        float2 f0 = __half22float2(sx);
        float2 f1 = __half22float2(sy);
        acc.x += f0.x; acc.y += f0.y; acc.z += f1.x; acc.w += f1.y;
        j += 8;
        if (nxt) { A0 = B0; A1 = B1; }
        have = nxt;
    }
    for (; j < e; j++) {
        int s = __ldg(&es[j]);
        uint2 u = __ldg(&h2[s * 32 + lane]);
        float2 a = __half22float2(U2H(u.x));
        float2 b = __half22float2(U2H(u.y));
        acc.x += a.x; acc.y += a.y; acc.z += b.x; acc.w += b.y;
    }

    // single fp16 plane, swizzled MMA tile layout
    int tile = gw >> 6, row = gw & 63;
    int col = lane * 4;
    uint32_t off = (uint32_t)(tile * 16384 + row * 256
                              + (((col >> 3) ^ (row & 7)) << 4) + (col & 7) * 2);
    __half2 p0 = __floats2half2_rn(acc.x, acc.y);
    __half2 p1 = __floats2half2_rn(acc.z, acc.w);
    uint2 u;
    u.x = reinterpret_cast<uint32_t&>(p0);
    u.y = reinterpret_cast<uint32_t&>(p1);
    *reinterpret_cast<uint2*>(reinterpret_cast<char*>(g_a16) + off) = u;
}

// ---------------- warp-MMA helpers ------------------------------------------
__device__ __forceinline__ uint32_t smem_u32(const void* p) {
    uint32_t a;
    asm("{ .reg .u64 t; cvta.to.shared.u64 t, %1; cvt.u32.u64 %0, t; }"
        : "=r"(a) : "l"(p));
    return a;
}
__device__ __forceinline__ void ldsm4(unsigned r[4], uint32_t addr) {
    asm volatile("ldmatrix.sync.aligned.m8n8.x4.shared.b16 {%0,%1,%2,%3}, [%4];"
                 : "=r"(r[0]), "=r"(r[1]), "=r"(r[2]), "=r"(r[3]) : "r"(addr));
}
__device__ __forceinline__ void mma16816(float c[4], const unsigned a[4],
                                         const unsigned b[2]) {
    asm volatile(
        "mma.sync.aligned.m16n8k16.row.col.f32.f16.f16.f32 "
        "{%0,%1,%2,%3}, {%4,%5,%6,%7}, {%8,%9}, {%0,%1,%2,%3};"
        : "+f"(c[0]), "+f"(c[1]), "+f"(c[2]), "+f"(c[3])
        : "r"(a[0]), "r"(a[1]), "r"(a[2]), "r"(a[3]), "r"(b[0]), "r"(b[1]));
}

// 64x128 @ 128x128 stage; warp = 32 rows x 32 cols (2 m-tiles x 4 n-tiles)
// A single fp16 plane; W fp16 hi/lo (2 products)
__device__ __forceinline__ void mma_stage(uint32_t aP,
                                          uint32_t wHi, uint32_t wLo,
                                          int mhalf, int nq, int lane,
                                          float c[2][4][4]) {
    #pragma unroll
    for (int mt = 0; mt < 2; mt++)
        #pragma unroll
        for (int nt = 0; nt < 4; nt++)
            #pragma unroll
            for (int q = 0; q < 4; q++) c[mt][nt][q] = 0.f;

    int m = lane >> 3, r = lane & 7;
    uint32_t aRow[2], bRow[2];
    #pragma unroll
    for (int mt = 0; mt < 2; mt++)
        aRow[mt] = (uint32_t)(mhalf * 32 + mt * 16 + (m & 1) * 8 + r) * 256;
    #pragma unroll
    for (int bt = 0; bt < 2; bt++)
        bRow[bt] = (uint32_t)(nq * 32 + bt * 16 + (m >> 1) * 8 + r) * 256;
    int aAdd = m >> 1, bAdd = m & 1;

    #pragma unroll
    for (int k = 0; k < 8; k++) {
        unsigned a[2][4], bh[2][4], bl[2][4];
        uint32_t ac = (uint32_t)(((k * 2 + aAdd) ^ r) << 4);
        uint32_t bc = (uint32_t)(((k * 2 + bAdd) ^ r) << 4);
        #pragma unroll
        for (int mt = 0; mt < 2; mt++)
            ldsm4(a[mt], aP + aRow[mt] + ac);
        #pragma unroll
        for (int bt = 0; bt < 2; bt++) {
            ldsm4(bh[bt], wHi + bRow[bt] + bc);
            ldsm4(bl[bt], wLo + bRow[bt] + bc);
        }
        #pragma unroll
        for (int mt = 0; mt < 2; mt++)
            #pragma unroll
            for (int nt = 0; nt < 4; nt++) {
                const unsigned* BH = bh[nt >> 1] + (nt & 1) * 2;
                const unsigned* BL = bl[nt >> 1] + (nt & 1) * 2;
                mma16816(c[mt][nt], a[mt], BH);
                mma16816(c[mt][nt], a[mt], BL);
            }
    }
}

__device__ __forceinline__ void store_h16(char* pA, int row, int col,
                                          float f0, float f1) {
    __half2 h = __floats2half2_rn(f0, f1);
    uint32_t off = (uint32_t)(row * 256 + (((col >> 3) ^ (row & 7)) << 4)
                              + (col & 7) * 2);
    *(__half2*)(pA + off) = h;
}

__device__ __forceinline__ void stcs2(float* p, float v0, float v1) {
    asm volatile("st.global.cs.v2.f32 [%0], {%1,%2};" :: "l"(p), "f"(v0), "f"(v1)
                 : "memory");
}
__device__ __forceinline__ void stcsh2(__half* p, float v0, float v1) {
    __half2 h = __floats2half2_rn(v0, v1);
    unsigned u = reinterpret_cast<unsigned&>(h);
    asm volatile("st.global.cs.u32 [%0], %1;" :: "l"(p), "r"(u) : "memory");
}

// ---------------- MMA kernel: plane copy -> MMA1 -> relu -> MMA2 ------------
// 256 threads, 64-row tile, 80KB smem -> 2 CTAs/SM.  (R10 design — best known)
__global__ void __launch_bounds__(256, 2) mma_kernel(
        const float* __restrict__ b1, const float* __restrict__ b2,
        float* __restrict__ hout32, __half* __restrict__ hout16,
        int widx, int relu2) {
    extern __shared__ char smem[];
    char* pA   = smem;             // 64 x 256B = 16KB
    char* pWhi = smem + 16384;     // 128 x 256B = 32KB
    char* pWlo = smem + 49152;     // 32KB

    int tid = threadIdx.x;
    int lane = tid & 31, wid = tid >> 5;
    int nodeBase = blockIdx.x * 64;

    // ---- stage W1 + A plane (linear copies; layouts pre-swizzled) ----
    {
        const float4* sh = (const float4*)g_whi[widx];
        const float4* sl = (const float4*)g_wlo[widx];
        const float4* aP = (const float4*)(g_a16 + (size_t)blockIdx.x * 8192);
        float4* dWh = (float4*)pWhi;
        float4* dWl = (float4*)pWlo;
        float4* dA  = (float4*)pA;
        #pragma unroll
        for (int i = 0; i < 4; i++) {
            int j = tid + 256 * i;
            dA[j] = aP[j];
        }
        #pragma unroll
        for (int i = 0; i < 8; i++) {
            int j = tid + 256 * i;
            dWh[j] = sh[j];
            dWl[j] = sl[j];
        }
    }
    __syncthreads();

    uint32_t aP = smem_u32(pA);
    uint32_t wHi = smem_u32(pWhi), wLo = smem_u32(pWlo);
    int mhalf = wid & 1;
    int nq = wid >> 1;
    int gid = lane >> 2, lc = (lane & 3) * 2;

    float c[2][4][4];
    mma_stage(aP, wHi, wLo, mhalf, nq, lane, c);
    __syncthreads();

    // ---- epilogue 1: relu(C+b1) -> fp16 into A plane ----
    #pragma unroll
    for (int mt = 0; mt < 2; mt++)
        #pragma unroll
        for (int nt = 0; nt < 4; nt++) {
            int col = nq * 32 + nt * 8 + lc;
            float2 bb = *(const float2*)&b1[col];
            int r0 = mhalf * 32 + mt * 16 + gid;
            float f0 = fmaxf(c[mt][nt][0] + bb.x, 0.f);
            float f1 = fmaxf(c[mt][nt][1] + bb.y, 0.f);
            float f2 = fmaxf(c[mt][nt][2] + bb.x, 0.f);
            float f3 = fmaxf(c[mt][nt][3] + bb.y, 0.f);
            store_h16(pA, r0,     col, f0, f1);
            store_h16(pA, r0 + 8, col, f2, f3);
        }

    // ---- stage W2 ----
    {
        const float4* sh = (const float4*)g_whi[widx + 1];
        const float4* sl = (const float4*)g_wlo[widx + 1];
        float4* dh = (float4*)pWhi;
        float4* dl = (float4*)pWlo;
        #pragma unroll
        for (int i = 0; i < 8; i++) {
            int j = tid + 256 * i;
            dh[j] = sh[j];
            dl[j] = sl[j];
        }
    }
    __syncthreads();

    mma_stage(aP, wHi, wLo, mhalf, nq, lane, c);

    // ---- epilogue 2: C + b2 (+relu) -> gmem ----
    #pragma unroll
    for (int mt = 0; mt < 2; mt++)
        #pragma unroll
        for (int nt = 0; nt < 4; nt++) {
            int col = nq * 32 + nt * 8 + lc;
            float2 bb = *(const float2*)&b2[col];
            float v0 = c[mt][nt][0] + bb.x;
            float v1 = c[mt][nt][1] + bb.y;
            float v2 = c[mt][nt][2] + bb.x;
            float v3 = c[mt][nt][3] + bb.y;
            if (relu2) {
                v0 = fmaxf(v0, 0.f); v1 = fmaxf(v1, 0.f);
                v2 = fmaxf(v2, 0.f); v3 = fmaxf(v3, 0.f);
            }
            int r0 = mhalf * 32 + mt * 16 + gid;
            int n0 = nodeBase + r0;
            int n1 = n0 + 8;
            if (relu2) {   // intermediate layers: fp16 activations
                if (n0 < NN) stcsh2(&hout16[n0 * DD + col], v0, v1);
                if (n1 < NN) stcsh2(&hout16[n1 * DD + col], v2, v3);
            } else {       // last layer: fp32 for pooling
                if (n0 < NN) stcs2(&hout32[n0 * DD + col], v0, v1);
                if (n1 < NN) stcs2(&hout32[n1 * DD + col], v2, v3);
            }
        }
}

// ---------------- mean pool over sorted batch + cleanup ----------------------
__device__ __forceinline__ int lbound_batch(const void* b, int val, int is64) {
    int lo = 0, hi = NN;
    if (is64) {
        const long long* p = (const long long*)b;
        long long v = val;
        while (lo < hi) { int mid = (lo + hi) >> 1; if (p[mid] < v) lo = mid + 1; else hi = mid; }
    } else {
        const int* p = (const int*)b;
        while (lo < hi) { int mid = (lo + hi) >> 1; if (p[mid] < val) lo = mid + 1; else hi = mid; }
    }
    return lo;
}

__global__ void pool_kernel(const float* __restrict__ h,
                            const void* __restrict__ batch,
                            const void* __restrict__ ei,
                            float* __restrict__ out) {
    // fused cleanup: restore invariants for the next kernel_launch call
    {
        int gtid = blockIdx.x * 512 + threadIdx.x;   // 65536 threads
        g_deg[gtid] = 0;
        int g2 = gtid + 65536;
        if (g2 < NN) g_deg[g2] = 0;
        if (gtid < NB) g_desc[gtid] = 0ULL;
    }
    __shared__ int s_is64;
    if (threadIdx.x == 0) s_is64 = detect64(ei);
    __syncthreads();
    int g = blockIdx.x;
    int d = threadIdx.x & 127;
    int sub = threadIdx.x >> 7;
    int start = lbound_batch(batch, g, s_is64);
    int end   = lbound_batch(batch, g + 1, s_is64);
    float acc = 0.f;
    for (int n = start + sub; n < end; n += 4)
        acc += h[n * DD + d];
    __shared__ float red[512];
    red[threadIdx.x] = acc;
    __syncthreads();
    if (sub == 0) {
        float s = (red[d] + red[d + 128]) + (red[d + 256] + red[d + 384]);
        int cnt = end - start;
        out[g * DD + d] = s / (float)(cnt > 0 ? cnt : 1);
    }
}

// ---------------- launch ------------------------------------------------------
extern "C" void kernel_launch(void* const* d_in, const int* in_sizes, int n_in,
                              void* d_out, int out_size) {
    const float* x = (const float*)d_in[0];
    const void* ei = d_in[1];
    const void* batch = d_in[2];
    const float *W1[3], *b1[3], *W2[3], *b2[3];
    for (int l = 0; l < 3; l++) {
        W1[l] = (const float*)d_in[3 + 4 * l];
        b1[l] = (const float*)d_in[4 + 4 * l];
        W2[l] = (const float*)d_in[5 + 4 * l];
        b2[l] = (const float*)d_in[6 + 4 * l];
    }
    float* out = (float*)d_out;

    cudaFuncSetAttribute(mma_kernel,
                         cudaFuncAttributeMaxDynamicSharedMemorySize, 81920);

    float* h;
    __half *xh, *hh0, *hh1;
    cudaGetSymbolAddress((void**)&h, g_h);
    cudaGetSymbolAddress((void**)&xh, g_xh);
    cudaGetSymbolAddress((void**)&hh0, g_hh0);
    cudaGetSymbolAddress((void**)&hh1, g_hh1);

    const int agg_blocks = (NN * 32 + 255) / 256;   // 12500

    pre_kernel<<<6 + HISTB + XCONVB, 512>>>(ei, x, W1[0], W2[0], W1[1], W2[1],
                                            W1[2], W2[2]);                       // 0
    scan_kernel<<<NB, 512>>>();                                                   // 1
    fill_kernel<<<NE / 512, 512>>>(ei);                                           // 2

    agg_kernel<<<agg_blocks, 256>>>(xh);                                          // 3 (profiled)
    mma_kernel<<<TLCNT, 256, 81920>>>(b1[0], b2[0], nullptr, hh0, 0, 1);          // 4
    agg_kernel<<<agg_blocks, 256>>>(hh0);                                         // 5
    mma_kernel<<<TLCNT, 256, 81920>>>(b1[1], b2[1], nullptr, hh1, 2, 1);          // 6
    agg_kernel<<<agg_blocks, 256>>>(hh1);                                         // 7
    mma_kernel<<<TLCNT, 256, 81920>>>(b1[2], b2[2], h, nullptr, 4, 0);            // 8

    pool_kernel<<<NG, 512>>>(h, batch, ei, out);                                  // 9
}

// round 15
// speedup vs baseline: 1.2273x; 1.2148x over previous
#include <cuda_runtime.h>
#include <cuda_bf16.h>
#include <cuda_fp16.h>
#include <cstdint>

#define NN 100000
#define NE 1600000
#define DD 128
#define NG 128
#define NB 196              // scan blocks: 196*512 >= NN
#define TLCNT 1563          // (NN+63)/64 tiles of 64 rows
#define HISTB 3125          // NE/512
#define XCONVB 3125         // NN*DD/4096

// ---------------- scratch (static device globals; zero-initialized) ---------
__device__ __align__(16) float g_h[NN * DD];        // final fp32 activations
__device__ __align__(16) __half g_xh[NN * DD];      // fp16 copy of input x
__device__ __align__(16) __half g_hh0[NN * DD];     // fp16 activations (layer0 out)
__device__ __align__(16) __half g_hh1[NN * DD];     // fp16 activations (layer1 out)
__device__ int g_deg[NN];
__device__ int g_rowptr[NN + 1];
__device__ int g_cursor[NN];
__device__ int g_esorted[NE];
__device__ unsigned long long g_desc[NB];
// aggregated tiles: single fp16 plane, swizzled MMA layout (+1 pad tile)
__device__ __align__(16) __half g_a16[(TLCNT + 1) * 8192];
// pre-transposed, pre-swizzled fp16 weights {W1_0,W2_0,W1_1,W2_1,W1_2,W2_2}
__device__ __align__(16) __half g_whi[6][16384];

__device__ __forceinline__ __half2 U2H(unsigned u) {
    return *reinterpret_cast<__half2*>(&u);
}

// ---------------- inline index-width detection ------------------------------
__device__ __forceinline__ int detect64(const void* p) {
    const unsigned* w = (const unsigned*)p;
    unsigned acc = 0;
    #pragma unroll
    for (int i = 0; i < 16; i++) acc |= w[2 * i + 1];
    return acc == 0u;
}

// ---------------- launch 0: weight prep + degree hist + x->fp16 -------------
__device__ __forceinline__ uint32_t w_off(int n, int k) {
    return (uint32_t)(n * 128 + (((k >> 3) ^ (n & 7)) << 3) + (k & 7));
}

__global__ void __launch_bounds__(512) pre_kernel(
        const void* __restrict__ ei, const float* __restrict__ x,
        const float* w0, const float* w1, const float* w2,
        const float* w3, const float* w4, const float* w5) {
    if (blockIdx.x < 6) {
        const float* src[6] = {w0, w1, w2, w3, w4, w5};
        const float* W = src[blockIdx.x];
        for (int i = threadIdx.x; i < 16384; i += 512) {
            int k = i >> 7, n = i & 127;
            g_whi[blockIdx.x][w_off(n, k)] = __float2half_rn(W[i]);
        }
        return;
    }
    if (blockIdx.x >= 6 + HISTB) {
        int base = (blockIdx.x - 6 - HISTB) * 4096 + threadIdx.x * 8;
        float4 a = __ldg((const float4*)(x + base));
        float4 b = __ldg((const float4*)(x + base + 4));
        __half2 p0 = __floats2half2_rn(a.x, a.y);
        __half2 p1 = __floats2half2_rn(a.z, a.w);
        __half2 p2 = __floats2half2_rn(b.x, b.y);
        __half2 p3 = __floats2half2_rn(b.z, b.w);
        uint4 u;
        u.x = reinterpret_cast<uint32_t&>(p0);
        u.y = reinterpret_cast<uint32_t&>(p1);
        u.z = reinterpret_cast<uint32_t&>(p2);
        u.w = reinterpret_cast<uint32_t&>(p3);
        *reinterpret_cast<uint4*>(g_xh + base) = u;
        return;
    }
    __shared__ int s_is64;
    if (threadIdx.x == 0) s_is64 = detect64(ei);
    __syncthreads();
    int e = (blockIdx.x - 6) * 512 + threadIdx.x;   // grid exact
    int dst = s_is64 ? (int)((const long long*)ei)[(long)NE + e]
                     : ((const int*)ei)[NE + e];
    atomicAdd(&g_deg[dst], 1);
}

// ---------------- launch 1: single-kernel exclusive scan ---------------------
__global__ void __launch_bounds__(512) scan_kernel() {
    int b = blockIdx.x, t = threadIdx.x;
    int idx = b * 512 + t;
    int v = (idx < NN) ? g_deg[idx] : 0;
    int lane = t & 31, w = t >> 5;
    int x = v;
    #pragma unroll
    for (int o = 1; o < 32; o <<= 1) {
        int u = __shfl_up_sync(~0u, x, o);
        if (lane >= o) x += u;
    }
    __shared__ int ws[16], wo[16];
    __shared__ int s_prefix, s_total;
    if (lane == 31) ws[w] = x;
    __syncthreads();
    if (t < 16) {
        int y = ws[t], z = y;
        #pragma unroll
        for (int o = 1; o < 16; o <<= 1) {
            int u = __shfl_up_sync(0xffffu, z, o, 16);
            if (t >= o) z += u;
        }
        wo[t] = z - y;
        if (t == 15) s_total = z;
    }
    __syncthreads();
    int incl = x + wo[w];
    if (t == 0)
        atomicExch(&g_desc[b], (1ULL << 32) | (unsigned)s_total);   // AGGREGATE
    if (t < 32) {
        long long running = 0;
        int i = b - 1 - t;
        while (true) {
            unsigned long long d = (2ULL << 32);
            if (i >= 0) {
                do { d = atomicAdd(&g_desc[i], 0ULL); } while ((d >> 32) == 0ULL);
            }
            int isPre = ((d >> 32) == 2ULL);
            unsigned pm = __ballot_sync(~0u, isPre);
            if (pm) {
                int fp = __ffs(pm) - 1;
                long long val = (t <= fp) ? (long long)(unsigned)d : 0;
                #pragma unroll
                for (int o = 16; o; o >>= 1) val += __shfl_down_sync(~0u, val, o);
                running += __shfl_sync(~0u, val, 0);
                break;
            } else {
                long long val = (long long)(unsigned)d;
                #pragma unroll
                for (int o = 16; o; o >>= 1) val += __shfl_down_sync(~0u, val, o);
                running += __shfl_sync(~0u, val, 0);
                i -= 32;
            }
        }
        if (t == 0) {
            s_prefix = (int)running;
            atomicExch(&g_desc[b],
                       (2ULL << 32) | (unsigned)(running + s_total));   // PREFIX
        }
    }
    __syncthreads();
    int excl = s_prefix + incl - v;
    if (idx < NN) { g_rowptr[idx] = excl; g_cursor[idx] = excl; }
    if (idx == NN - 1) g_rowptr[NN] = s_prefix + incl;
}

// ---------------- launch 2: CSR fill ----------------------------------------
__global__ void __launch_bounds__(512) fill_kernel(const void* __restrict__ ei) {
    __shared__ int s_is64;
    if (threadIdx.x == 0) s_is64 = detect64(ei);
    __syncthreads();
    int e = blockIdx.x * 512 + threadIdx.x;   // grid exact
    int dst, src;
    if (s_is64) {
        dst = (int)((const long long*)ei)[(long)NE + e];
        src = (int)((const long long*)ei)[e];
    } else {
        dst = ((const int*)ei)[NE + e];
        src = ((const int*)ei)[e];
    }
    int pos = atomicAdd(&g_cursor[dst], 1);
    g_esorted[pos] = src;
}

// ---------------- aggregation: warp-per-node, fp16 tree (R10 form) ----------
__global__ void __launch_bounds__(256) agg_kernel(const __half* __restrict__ hin) {
    int gw = (blockIdx.x * 256 + threadIdx.x) >> 5;   // node index
    if (gw >= NN) return;
    int lane = threadIdx.x & 31;
    const uint2* h2 = (const uint2*)hin;
    const int* es = g_esorted;

    float4 acc;
    {
        uint2 u = __ldg(&h2[gw * 32 + lane]);
        float2 a = __half22float2(U2H(u.x));
        float2 b = __half22float2(U2H(u.y));
        acc = make_float4(a.x, a.y, b.x, b.y);
    }
    int j = g_rowptr[gw], e = g_rowptr[gw + 1];

    int i0, i1, i2, i3, i4, i5, i6, i7;
    bool have = (j + 8 <= e);
    if (have) {
        i0 = __ldg(&es[j]);     i1 = __ldg(&es[j + 1]);
        i2 = __ldg(&es[j + 2]); i3 = __ldg(&es[j + 3]);
        i4 = __ldg(&es[j + 4]); i5 = __ldg(&es[j + 5]);
        i6 = __ldg(&es[j + 6]); i7 = __ldg(&es[j + 7]);
    }
    #pragma unroll 1
    while (have) {
        uint2 uu[8];
        uu[0] = __ldg(&h2[i0 * 32 + lane]);
        uu[1] = __ldg(&h2[i1 * 32 + lane]);
        uu[2] = __ldg(&h2[i2 * 32 + lane]);
        uu[3] = __ldg(&h2[i3 * 32 + lane]);
        uu[4] = __ldg(&h2[i4 * 32 + lane]);
        uu[5] = __ldg(&h2[i5 * 32 + lane]);
        uu[6] = __ldg(&h2[i6 * 32 + lane]);
        uu[7] = __ldg(&h2[i7 * 32 + lane]);
        bool nxt = (j + 16 <= e);
        int x0, x1, x2, x3, x4, x5, x6, x7;
        if (nxt) {
            x0 = __ldg(&es[j + 8]);  x1 = __ldg(&es[j + 9]);
            x2 = __ldg(&es[j + 10]); x3 = __ldg(&es[j + 11]);
            x4 = __ldg(&es[j + 12]); x5 = __ldg(&es[j + 13]);
            x6 = __ldg(&es[j + 14]); x7 = __ldg(&es[j + 15]);
        }
        __half2 sx = __hadd2(__hadd2(__hadd2(U2H(uu[0].x), U2H(uu[1].x)),
                                     __hadd2(U2H(uu[2].x), U2H(uu[3].x))),
                             __hadd2(__hadd2(U2H(uu[4].x), U2H(uu[5].x)),
                                     __hadd2(U2H(uu[6].x), U2H(uu[7].x))));
        __half2 sy = __hadd2(__hadd2(__hadd2(U2H(uu[0].y), U2H(uu[1].y)),
                                     __hadd2(U2H(uu[2].y), U2H(uu[3].y))),
                             __hadd2(__hadd2(U2H(uu[4].y), U2H(uu[5].y)),
                                     __hadd2(U2H(uu[6].y), U2H(uu[7].y))));
        float2 f0 = __half22float2(sx);
        float2 f1 = __half22float2(sy);
        acc.x += f0.x; acc.y += f0.y; acc.z += f1.x; acc.w += f1.y;
        j += 8;
        if (nxt) { i0 = x0; i1 = x1; i2 = x2; i3 = x3;
                   i4 = x4; i5 = x5; i6 = x6; i7 = x7; }
        have = nxt;
    }
    for (; j < e; j++) {
        int s = __ldg(&es[j]);
        uint2 u = __ldg(&h2[s * 32 + lane]);
        float2 a = __half22float2(U2H(u.x));
        float2 b = __half22float2(U2H(u.y));
        acc.x += a.x; acc.y += a.y; acc.z += b.x; acc.w += b.y;
    }

    int tile = gw >> 6, row = gw & 63;
    int col = lane * 4;
    uint32_t off = (uint32_t)(tile * 16384 + row * 256
                              + (((col >> 3) ^ (row & 7)) << 4) + (col & 7) * 2);
    __half2 p0 = __floats2half2_rn(acc.x, acc.y);
    __half2 p1 = __floats2half2_rn(acc.z, acc.w);
    uint2 u;
    u.x = reinterpret_cast<uint32_t&>(p0);
    u.y = reinterpret_cast<uint32_t&>(p1);
    *reinterpret_cast<uint2*>(reinterpret_cast<char*>(g_a16) + off) = u;
}

// ---------------- warp-MMA helpers ------------------------------------------
__device__ __forceinline__ uint32_t smem_u32(const void* p) {
    uint32_t a;
    asm("{ .reg .u64 t; cvta.to.shared.u64 t, %1; cvt.u32.u64 %0, t; }"
        : "=r"(a) : "l"(p));
    return a;
}
__device__ __forceinline__ void ldsm4(unsigned r[4], uint32_t addr) {
    asm volatile("ldmatrix.sync.aligned.m8n8.x4.shared.b16 {%0,%1,%2,%3}, [%4];"
                 : "=r"(r[0]), "=r"(r[1]), "=r"(r[2]), "=r"(r[3]) : "r"(addr));
}
__device__ __forceinline__ void mma16816(float c[4], const unsigned a[4],
                                         const unsigned b[2]) {
    asm volatile(
        "mma.sync.aligned.m16n8k16.row.col.f32.f16.f16.f32 "
        "{%0,%1,%2,%3}, {%4,%5,%6,%7}, {%8,%9}, {%0,%1,%2,%3};"
        : "+f"(c[0]), "+f"(c[1]), "+f"(c[2]), "+f"(c[3])
        : "r"(a[0]), "r"(a[1]), "r"(a[2]), "r"(a[3]), "r"(b[0]), "r"(b[1]));
}

// 64x128 @ 128x128 stage; warp = 32 rows x 32 cols; SINGLE fp16 product
__device__ __forceinline__ void mma_stage(uint32_t aP, uint32_t wP,
                                          int mhalf, int nq, int lane,
                                          float c[2][4][4]) {
    #pragma unroll
    for (int mt = 0; mt < 2; mt++)
        #pragma unroll
        for (int nt = 0; nt < 4; nt++)
            #pragma unroll
            for (int q = 0; q < 4; q++) c[mt][nt][q] = 0.f;

    int m = lane >> 3, r = lane & 7;
    uint32_t aRow[2], bRow[2];
    #pragma unroll
    for (int mt = 0; mt < 2; mt++)
        aRow[mt] = (uint32_t)(mhalf * 32 + mt * 16 + (m & 1) * 8 + r) * 256;
    #pragma unroll
    for (int bt = 0; bt < 2; bt++)
        bRow[bt] = (uint32_t)(nq * 32 + bt * 16 + (m >> 1) * 8 + r) * 256;
    int aAdd = m >> 1, bAdd = m & 1;

    #pragma unroll
    for (int k = 0; k < 8; k++) {
        unsigned a[2][4], bh[2][4];
        uint32_t ac = (uint32_t)(((k * 2 + aAdd) ^ r) << 4);
        uint32_t bc = (uint32_t)(((k * 2 + bAdd) ^ r) << 4);
        #pragma unroll
        for (int mt = 0; mt < 2; mt++)
            ldsm4(a[mt], aP + aRow[mt] + ac);
        #pragma unroll
        for (int bt = 0; bt < 2; bt++)
            ldsm4(bh[bt], wP + bRow[bt] + bc);
        #pragma unroll
        for (int mt = 0; mt < 2; mt++)
            #pragma unroll
            for (int nt = 0; nt < 4; nt++)
                mma16816(c[mt][nt], a[mt], bh[nt >> 1] + (nt & 1) * 2);
    }
}

__device__ __forceinline__ void store_h16(char* pA, int row, int col,
                                          float f0, float f1) {
    __half2 h = __floats2half2_rn(f0, f1);
    uint32_t off = (uint32_t)(row * 256 + (((col >> 3) ^ (row & 7)) << 4)
                              + (col & 7) * 2);
    *(__half2*)(pA + off) = h;
}

__device__ __forceinline__ void stcs2(float* p, float v0, float v1) {
    asm volatile("st.global.cs.v2.f32 [%0], {%1,%2};" :: "l"(p), "f"(v0), "f"(v1)
                 : "memory");
}
__device__ __forceinline__ void stcsh2(__half* p, float v0, float v1) {
    __half2 h = __floats2half2_rn(v0, v1);
    unsigned u = reinterpret_cast<unsigned&>(h);
    asm volatile("st.global.cs.u32 [%0], %1;" :: "l"(p), "r"(u) : "memory");
}

// ---------------- MMA kernel: plane copy -> MMA1 -> relu -> MMA2 ------------
// 256 threads, 64-row tile, 48KB smem -> 3 CTAs/SM.
__global__ void __launch_bounds__(256, 3) mma_kernel(
        const float* __restrict__ b1, const float* __restrict__ b2,
        float* __restrict__ hout32, __half* __restrict__ hout16,
        int widx, int relu2) {
    extern __shared__ char smem[];
    char* pA = smem;              // 64 x 256B = 16KB
    char* pW = smem + 16384;      // 128 x 256B = 32KB

    int tid = threadIdx.x;
    int lane = tid & 31, wid = tid >> 5;
    int nodeBase = blockIdx.x * 64;

    // ---- stage W1 + A plane (linear copies; layouts pre-swizzled) ----
    {
        const float4* sw = (const float4*)g_whi[widx];
        const float4* aP = (const float4*)(g_a16 + (size_t)blockIdx.x * 8192);
        float4* dW = (float4*)pW;
        float4* dA = (float4*)pA;
        #pragma unroll
        for (int i = 0; i < 4; i++) {
            int j = tid + 256 * i;
            dA[j] = aP[j];
        }
        #pragma unroll
        for (int i = 0; i < 8; i++) {
            int j = tid + 256 * i;
            dW[j] = sw[j];
        }
    }
    __syncthreads();

    uint32_t aP = smem_u32(pA);
    uint32_t wP = smem_u32(pW);
    int mhalf = wid & 1;
    int nq = wid >> 1;
    int gid = lane >> 2, lc = (lane & 3) * 2;

    float c[2][4][4];
    mma_stage(aP, wP, mhalf, nq, lane, c);
    __syncthreads();

    // ---- epilogue 1: relu(C+b1) -> fp16 into A plane ----
    #pragma unroll
    for (int mt = 0; mt < 2; mt++)
        #pragma unroll
        for (int nt = 0; nt < 4; nt++) {
            int col = nq * 32 + nt * 8 + lc;
            float2 bb = *(const float2*)&b1[col];
            int r0 = mhalf * 32 + mt * 16 + gid;
            float f0 = fmaxf(c[mt][nt][0] + bb.x, 0.f);
            float f1 = fmaxf(c[mt][nt][1] + bb.y, 0.f);
            float f2 = fmaxf(c[mt][nt][2] + bb.x, 0.f);
            float f3 = fmaxf(c[mt][nt][3] + bb.y, 0.f);
            store_h16(pA, r0,     col, f0, f1);
            store_h16(pA, r0 + 8, col, f2, f3);
        }

    // ---- stage W2 into the same W buffer (same barrier window) ----
    {
        const float4* sw = (const float4*)g_whi[widx + 1];
        float4* dW = (float4*)pW;
        #pragma unroll
        for (int i = 0; i < 8; i++) {
            int j = tid + 256 * i;
            dW[j] = sw[j];
        }
    }
    __syncthreads();

    mma_stage(aP, wP, mhalf, nq, lane, c);

    // ---- epilogue 2: C + b2 (+relu) -> gmem ----
    #pragma unroll
    for (int mt = 0; mt < 2; mt++)
        #pragma unroll
        for (int nt = 0; nt < 4; nt++) {
            int col = nq * 32 + nt * 8 + lc;
            float2 bb = *(const float2*)&b2[col];
            float v0 = c[mt][nt][0] + bb.x;
            float v1 = c[mt][nt][1] + bb.y;
            float v2 = c[mt][nt][2] + bb.x;
            float v3 = c[mt][nt][3] + bb.y;
            if (relu2) {
                v0 = fmaxf(v0, 0.f); v1 = fmaxf(v1, 0.f);
                v2 = fmaxf(v2, 0.f); v3 = fmaxf(v3, 0.f);
            }
            int r0 = mhalf * 32 + mt * 16 + gid;
            int n0 = nodeBase + r0;
            int n1 = n0 + 8;
            if (relu2) {   // intermediate layers: fp16 activations
                if (n0 < NN) stcsh2(&hout16[n0 * DD + col], v0, v1);
                if (n1 < NN) stcsh2(&hout16[n1 * DD + col], v2, v3);
            } else {       // last layer: fp32 for pooling
                if (n0 < NN) stcs2(&hout32[n0 * DD + col], v0, v1);
                if (n1 < NN) stcs2(&hout32[n1 * DD + col], v2, v3);
            }
        }
}

// ---------------- mean pool over sorted batch + cleanup ----------------------
__device__ __forceinline__ int lbound_batch(const void* b, int val, int is64) {
    int lo = 0, hi = NN;
    if (is64) {
        const long long* p = (const long long*)b;
        long long v = val;
        while (lo < hi) { int mid = (lo + hi) >> 1; if (p[mid] < v) lo = mid + 1; else hi = mid; }
    } else {
        const int* p = (const int*)b;
        while (lo < hi) { int mid = (lo + hi) >> 1; if (p[mid] < val) lo = mid + 1; else hi = mid; }
    }
    return lo;
}

__global__ void pool_kernel(const float* __restrict__ h,
                            const void* __restrict__ batch,
                            const void* __restrict__ ei,
                            float* __restrict__ out) {
    // fused cleanup: restore invariants for the next kernel_launch call
    {
        int gtid = blockIdx.x * 512 + threadIdx.x;   // 65536 threads
        g_deg[gtid] = 0;
        int g2 = gtid + 65536;
        if (g2 < NN) g_deg[g2] = 0;
        if (gtid < NB) g_desc[gtid] = 0ULL;
    }
    __shared__ int s_is64;
    if (threadIdx.x == 0) s_is64 = detect64(ei);
    __syncthreads();
    int g = blockIdx.x;
    int d = threadIdx.x & 127;
    int sub = threadIdx.x >> 7;
    int start = lbound_batch(batch, g, s_is64);
    int end   = lbound_batch(batch, g + 1, s_is64);
    float acc = 0.f;
    for (int n = start + sub; n < end; n += 4)
        acc += h[n * DD + d];
    __shared__ float red[512];
    red[threadIdx.x] = acc;
    __syncthreads();
    if (sub == 0) {
        float s = (red[d] + red[d + 128]) + (red[d + 256] + red[d + 384]);
        int cnt = end - start;
        out[g * DD + d] = s / (float)(cnt > 0 ? cnt : 1);
    }
}

// ---------------- launch ------------------------------------------------------
extern "C" void kernel_launch(void* const* d_in, const int* in_sizes, int n_in,
                              void* d_out, int out_size) {
    const float* x = (const float*)d_in[0];
    const void* ei = d_in[1];
    const void* batch = d_in[2];
    const float *W1[3], *b1[3], *W2[3], *b2[3];
    for (int l = 0; l < 3; l++) {
        W1[l] = (const float*)d_in[3 + 4 * l];
        b1[l] = (const float*)d_in[4 + 4 * l];
        W2[l] = (const float*)d_in[5 + 4 * l];
        b2[l] = (const float*)d_in[6 + 4 * l];
    }
    float* out = (float*)d_out;

    cudaFuncSetAttribute(mma_kernel,
                         cudaFuncAttributeMaxDynamicSharedMemorySize, 49152);

    float* h;
    __half *xh, *hh0, *hh1;
    cudaGetSymbolAddress((void**)&h, g_h);
    cudaGetSymbolAddress((void**)&xh, g_xh);
    cudaGetSymbolAddress((void**)&hh0, g_hh0);
    cudaGetSymbolAddress((void**)&hh1, g_hh1);

    const int agg_blocks = (NN * 32 + 255) / 256;   // 12500

    pre_kernel<<<6 + HISTB + XCONVB, 512>>>(ei, x, W1[0], W2[0], W1[1], W2[1],
                                            W1[2], W2[2]);                       // 0
    scan_kernel<<<NB, 512>>>();                                                   // 1
    fill_kernel<<<NE / 512, 512>>>(ei);                                           // 2

    agg_kernel<<<agg_blocks, 256>>>(xh);                                          // 3 (profiled)
    mma_kernel<<<TLCNT, 256, 49152>>>(b1[0], b2[0], nullptr, hh0, 0, 1);          // 4
    agg_kernel<<<agg_blocks, 256>>>(hh0);                                         // 5
    mma_kernel<<<TLCNT, 256, 49152>>>(b1[1], b2[1], nullptr, hh1, 2, 1);          // 6
    agg_kernel<<<agg_blocks, 256>>>(hh1);                                         // 7
    mma_kernel<<<TLCNT, 256, 49152>>>(b1[2], b2[2], h, nullptr, 4, 0);            // 8

    pool_kernel<<<NG, 512>>>(h, batch, ei, out);                                  // 9
}

// round 16
// speedup vs baseline: 1.3107x; 1.0680x over previous
#include <cuda_runtime.h>
#include <cuda_bf16.h>
#include <cuda_fp16.h>
#include <cstdint>

#define NN 100000
#define NE 1600000
#define DD 128
#define NG 128
#define NB 196              // scan blocks: 196*512 >= NN
#define TLCNT 1563          // (NN+63)/64 tiles of 64 rows
#define HISTB 3125          // NE/512
#define XCONVB 3125         // NN*DD/4096

// ---------------- scratch (static device globals; zero-initialized) ---------
__device__ __align__(16) __half g_xh[NN * DD];      // fp16 copy of input x
__device__ __align__(16) __half g_hh0[NN * DD];     // fp16 activations (L0 / L2 out)
__device__ __align__(16) __half g_hh1[NN * DD];     // fp16 activations (L1 out)
__device__ int g_deg[NN];
__device__ int g_rowptr[NN + 1];
__device__ int g_cursor[NN];
__device__ int g_esorted[NE];
__device__ unsigned long long g_desc[NB];
// aggregated tiles: single fp16 plane, swizzled MMA layout (+1 pad tile)
__device__ __align__(16) __half g_a16[(TLCNT + 1) * 8192];
// pre-transposed, pre-swizzled fp16 weights {W1_0,W2_0,W1_1,W2_1,W1_2,W2_2}
__device__ __align__(16) __half g_whi[6][16384];

__device__ __forceinline__ __half2 U2H(unsigned u) {
    return *reinterpret_cast<__half2*>(&u);
}

// ---------------- inline index-width detection ------------------------------
__device__ __forceinline__ int detect64(const void* p) {
    const unsigned* w = (const unsigned*)p;
    unsigned acc = 0;
    #pragma unroll
    for (int i = 0; i < 16; i++) acc |= w[2 * i + 1];
    return acc == 0u;
}

// ---------------- launch 0: weight prep + degree hist + x->fp16 -------------
__device__ __forceinline__ uint32_t w_off(int n, int k) {
    return (uint32_t)(n * 128 + (((k >> 3) ^ (n & 7)) << 3) + (k & 7));
}

__global__ void __launch_bounds__(512) pre_kernel(
        const void* __restrict__ ei, const float* __restrict__ x,
        const float* w0, const float* w1, const float* w2,
        const float* w3, const float* w4, const float* w5) {
    if (blockIdx.x < 6) {
        const float* src[6] = {w0, w1, w2, w3, w4, w5};
        const float* W = src[blockIdx.x];
        for (int i = threadIdx.x; i < 16384; i += 512) {
            int k = i >> 7, n = i & 127;
            g_whi[blockIdx.x][w_off(n, k)] = __float2half_rn(W[i]);
        }
        return;
    }
    if (blockIdx.x >= 6 + HISTB) {
        int base = (blockIdx.x - 6 - HISTB) * 4096 + threadIdx.x * 8;
        float4 a = __ldg((const float4*)(x + base));
        float4 b = __ldg((const float4*)(x + base + 4));
        __half2 p0 = __floats2half2_rn(a.x, a.y);
        __half2 p1 = __floats2half2_rn(a.z, a.w);
        __half2 p2 = __floats2half2_rn(b.x, b.y);
        __half2 p3 = __floats2half2_rn(b.z, b.w);
        uint4 u;
        u.x = reinterpret_cast<uint32_t&>(p0);
        u.y = reinterpret_cast<uint32_t&>(p1);
        u.z = reinterpret_cast<uint32_t&>(p2);
        u.w = reinterpret_cast<uint32_t&>(p3);
        *reinterpret_cast<uint4*>(g_xh + base) = u;
        return;
    }
    __shared__ int s_is64;
    if (threadIdx.x == 0) s_is64 = detect64(ei);
    __syncthreads();
    int e = (blockIdx.x - 6) * 512 + threadIdx.x;   // grid exact
    int dst = s_is64 ? (int)((const long long*)ei)[(long)NE + e]
                     : ((const int*)ei)[NE + e];
    atomicAdd(&g_deg[dst], 1);
}

// ---------------- launch 1: single-kernel exclusive scan ---------------------
__global__ void __launch_bounds__(512) scan_kernel() {
    int b = blockIdx.x, t = threadIdx.x;
    int idx = b * 512 + t;
    int v = (idx < NN) ? g_deg[idx] : 0;
    int lane = t & 31, w = t >> 5;
    int x = v;
    #pragma unroll
    for (int o = 1; o < 32; o <<= 1) {
        int u = __shfl_up_sync(~0u, x, o);
        if (lane >= o) x += u;
    }
    __shared__ int ws[16], wo[16];
    __shared__ int s_prefix, s_total;
    if (lane == 31) ws[w] = x;
    __syncthreads();
    if (t < 16) {
        int y = ws[t], z = y;
        #pragma unroll
        for (int o = 1; o < 16; o <<= 1) {
            int u = __shfl_up_sync(0xffffu, z, o, 16);
            if (t >= o) z += u;
        }
        wo[t] = z - y;
        if (t == 15) s_total = z;
    }
    __syncthreads();
    int incl = x + wo[w];
    if (t == 0)
        atomicExch(&g_desc[b], (1ULL << 32) | (unsigned)s_total);   // AGGREGATE
    if (t < 32) {
        long long running = 0;
        int i = b - 1 - t;
        while (true) {
            unsigned long long d = (2ULL << 32);
            if (i >= 0) {
                do { d = atomicAdd(&g_desc[i], 0ULL); } while ((d >> 32) == 0ULL);
            }
            int isPre = ((d >> 32) == 2ULL);
            unsigned pm = __ballot_sync(~0u, isPre);
            if (pm) {
                int fp = __ffs(pm) - 1;
                long long val = (t <= fp) ? (long long)(unsigned)d : 0;
                #pragma unroll
                for (int o = 16; o; o >>= 1) val += __shfl_down_sync(~0u, val, o);
                running += __shfl_sync(~0u, val, 0);
                break;
            } else {
                long long val = (long long)(unsigned)d;
                #pragma unroll
                for (int o = 16; o; o >>= 1) val += __shfl_down_sync(~0u, val, o);
                running += __shfl_sync(~0u, val, 0);
                i -= 32;
            }
        }
        if (t == 0) {
            s_prefix = (int)running;
            atomicExch(&g_desc[b],
                       (2ULL << 32) | (unsigned)(running + s_total));   // PREFIX
        }
    }
    __syncthreads();
    int excl = s_prefix + incl - v;
    if (idx < NN) { g_rowptr[idx] = excl; g_cursor[idx] = excl; }
    if (idx == NN - 1) g_rowptr[NN] = s_prefix + incl;
}

// ---------------- launch 2: CSR fill ----------------------------------------
__global__ void __launch_bounds__(512) fill_kernel(const void* __restrict__ ei) {
    __shared__ int s_is64;
    if (threadIdx.x == 0) s_is64 = detect64(ei);
    __syncthreads();
    int e = blockIdx.x * 512 + threadIdx.x;   // grid exact
    int dst, src;
    if (s_is64) {
        dst = (int)((const long long*)ei)[(long)NE + e];
        src = (int)((const long long*)ei)[e];
    } else {
        dst = ((const int*)ei)[NE + e];
        src = ((const int*)ei)[e];
    }
    int pos = atomicAdd(&g_cursor[dst], 1);
    g_esorted[pos] = src;
}

// ---------------- aggregation: warp-per-node, all-fp16 accumulation ---------
__global__ void __launch_bounds__(256) agg_kernel(const __half* __restrict__ hin) {
    int gw = (blockIdx.x * 256 + threadIdx.x) >> 5;   // node index
    if (gw >= NN) return;
    int lane = threadIdx.x & 31;
    const uint2* h2 = (const uint2*)hin;
    const int* es = g_esorted;

    __half2 accx, accy;
    {
        uint2 u = __ldg(&h2[gw * 32 + lane]);
        accx = U2H(u.x);
        accy = U2H(u.y);
    }
    int j = g_rowptr[gw], e = g_rowptr[gw + 1];

    int i0, i1, i2, i3, i4, i5, i6, i7;
    bool have = (j + 8 <= e);
    if (have) {
        i0 = __ldg(&es[j]);     i1 = __ldg(&es[j + 1]);
        i2 = __ldg(&es[j + 2]); i3 = __ldg(&es[j + 3]);
        i4 = __ldg(&es[j + 4]); i5 = __ldg(&es[j + 5]);
        i6 = __ldg(&es[j + 6]); i7 = __ldg(&es[j + 7]);
    }
    #pragma unroll 1
    while (have) {
        uint2 uu[8];
        uu[0] = __ldg(&h2[i0 * 32 + lane]);
        uu[1] = __ldg(&h2[i1 * 32 + lane]);
        uu[2] = __ldg(&h2[i2 * 32 + lane]);
        uu[3] = __ldg(&h2[i3 * 32 + lane]);
        uu[4] = __ldg(&h2[i4 * 32 + lane]);
        uu[5] = __ldg(&h2[i5 * 32 + lane]);
        uu[6] = __ldg(&h2[i6 * 32 + lane]);
        uu[7] = __ldg(&h2[i7 * 32 + lane]);
        bool nxt = (j + 16 <= e);
        int x0, x1, x2, x3, x4, x5, x6, x7;
        if (nxt) {
            x0 = __ldg(&es[j + 8]);  x1 = __ldg(&es[j + 9]);
            x2 = __ldg(&es[j + 10]); x3 = __ldg(&es[j + 11]);
            x4 = __ldg(&es[j + 12]); x5 = __ldg(&es[j + 13]);
            x6 = __ldg(&es[j + 14]); x7 = __ldg(&es[j + 15]);
        }
        // fp16 tree sum of 8 edges; fp16 running accumulate (noise pools away)
        __half2 sx = __hadd2(__hadd2(__hadd2(U2H(uu[0].x), U2H(uu[1].x)),
                                     __hadd2(U2H(uu[2].x), U2H(uu[3].x))),
                             __hadd2(__hadd2(U2H(uu[4].x), U2H(uu[5].x)),
                                     __hadd2(U2H(uu[6].x), U2H(uu[7].x))));
        __half2 sy = __hadd2(__hadd2(__hadd2(U2H(uu[0].y), U2H(uu[1].y)),
                                     __hadd2(U2H(uu[2].y), U2H(uu[3].y))),
                             __hadd2(__hadd2(U2H(uu[4].y), U2H(uu[5].y)),
                                     __hadd2(U2H(uu[6].y), U2H(uu[7].y))));
        accx = __hadd2(accx, sx);
        accy = __hadd2(accy, sy);
        j += 8;
        if (nxt) { i0 = x0; i1 = x1; i2 = x2; i3 = x3;
                   i4 = x4; i5 = x5; i6 = x6; i7 = x7; }
        have = nxt;
    }
    for (; j < e; j++) {
        int s = __ldg(&es[j]);
        uint2 u = __ldg(&h2[s * 32 + lane]);
        accx = __hadd2(accx, U2H(u.x));
        accy = __hadd2(accy, U2H(u.y));
    }

    // single fp16 plane, swizzled MMA tile layout
    int tile = gw >> 6, row = gw & 63;
    int col = lane * 4;
    uint32_t off = (uint32_t)(tile * 16384 + row * 256
                              + (((col >> 3) ^ (row & 7)) << 4) + (col & 7) * 2);
    uint2 u;
    u.x = reinterpret_cast<uint32_t&>(accx);
    u.y = reinterpret_cast<uint32_t&>(accy);
    *reinterpret_cast<uint2*>(reinterpret_cast<char*>(g_a16) + off) = u;
}

// ---------------- warp-MMA helpers ------------------------------------------
__device__ __forceinline__ uint32_t smem_u32(const void* p) {
    uint32_t a;
    asm("{ .reg .u64 t; cvta.to.shared.u64 t, %1; cvt.u32.u64 %0, t; }"
        : "=r"(a) : "l"(p));
    return a;
}
__device__ __forceinline__ void ldsm4(unsigned r[4], uint32_t addr) {
    asm volatile("ldmatrix.sync.aligned.m8n8.x4.shared.b16 {%0,%1,%2,%3}, [%4];"
                 : "=r"(r[0]), "=r"(r[1]), "=r"(r[2]), "=r"(r[3]) : "r"(addr));
}
__device__ __forceinline__ void mma16816(float c[4], const unsigned a[4],
                                         const unsigned b[2]) {
    asm volatile(
        "mma.sync.aligned.m16n8k16.row.col.f32.f16.f16.f32 "
        "{%0,%1,%2,%3}, {%4,%5,%6,%7}, {%8,%9}, {%0,%1,%2,%3};"
        : "+f"(c[0]), "+f"(c[1]), "+f"(c[2]), "+f"(c[3])
        : "r"(a[0]), "r"(a[1]), "r"(a[2]), "r"(a[3]), "r"(b[0]), "r"(b[1]));
}

// 64x128 @ 128x128 stage; warp = 32 rows x 32 cols; single fp16 product
__device__ __forceinline__ void mma_stage(uint32_t aP, uint32_t wP,
                                          int mhalf, int nq, int lane,
                                          float c[2][4][4]) {
    #pragma unroll
    for (int mt = 0; mt < 2; mt++)
        #pragma unroll
        for (int nt = 0; nt < 4; nt++)
            #pragma unroll
            for (int q = 0; q < 4; q++) c[mt][nt][q] = 0.f;

    int m = lane >> 3, r = lane & 7;
    uint32_t aRow[2], bRow[2];
    #pragma unroll
    for (int mt = 0; mt < 2; mt++)
        aRow[mt] = (uint32_t)(mhalf * 32 + mt * 16 + (m & 1) * 8 + r) * 256;
    #pragma unroll
    for (int bt = 0; bt < 2; bt++)
        bRow[bt] = (uint32_t)(nq * 32 + bt * 16 + (m >> 1) * 8 + r) * 256;
    int aAdd = m >> 1, bAdd = m & 1;

    #pragma unroll
    for (int k = 0; k < 8; k++) {
        unsigned a[2][4], bh[2][4];
        uint32_t ac = (uint32_t)(((k * 2 + aAdd) ^ r) << 4);
        uint32_t bc = (uint32_t)(((k * 2 + bAdd) ^ r) << 4);
        #pragma unroll
        for (int mt = 0; mt < 2; mt++)
            ldsm4(a[mt], aP + aRow[mt] + ac);
        #pragma unroll
        for (int bt = 0; bt < 2; bt++)
            ldsm4(bh[bt], wP + bRow[bt] + bc);
        #pragma unroll
        for (int mt = 0; mt < 2; mt++)
            #pragma unroll
            for (int nt = 0; nt < 4; nt++)
                mma16816(c[mt][nt], a[mt], bh[nt >> 1] + (nt & 1) * 2);
    }
}

__device__ __forceinline__ void store_h16(char* pA, int row, int col,
                                          float f0, float f1) {
    __half2 h = __floats2half2_rn(f0, f1);
    uint32_t off = (uint32_t)(row * 256 + (((col >> 3) ^ (row & 7)) << 4)
                              + (col & 7) * 2);
    *(__half2*)(pA + off) = h;
}

__device__ __forceinline__ void stcsh2(__half* p, float v0, float v1) {
    __half2 h = __floats2half2_rn(v0, v1);
    unsigned u = reinterpret_cast<unsigned&>(h);
    asm volatile("st.global.cs.u32 [%0], %1;" :: "l"(p), "r"(u) : "memory");
}

// ---------------- MMA kernel: plane copy -> MMA1 -> relu -> MMA2 ------------
// 256 threads, 64-row tile, 48KB smem -> 3 CTAs/SM. fp16 output always.
__global__ void __launch_bounds__(256, 3) mma_kernel(
        const float* __restrict__ b1, const float* __restrict__ b2,
        __half* __restrict__ hout16, int widx, int relu2) {
    extern __shared__ char smem[];
    char* pA = smem;              // 64 x 256B = 16KB
    char* pW = smem + 16384;      // 128 x 256B = 32KB

    int tid = threadIdx.x;
    int lane = tid & 31, wid = tid >> 5;
    int nodeBase = blockIdx.x * 64;

    // ---- stage W1 + A plane (linear copies; layouts pre-swizzled) ----
    {
        const float4* sw = (const float4*)g_whi[widx];
        const float4* aP = (const float4*)(g_a16 + (size_t)blockIdx.x * 8192);
        float4* dW = (float4*)pW;
        float4* dA = (float4*)pA;
        #pragma unroll
        for (int i = 0; i < 4; i++) {
            int j = tid + 256 * i;
            dA[j] = aP[j];
        }
        #pragma unroll
        for (int i = 0; i < 8; i++) {
            int j = tid + 256 * i;
            dW[j] = sw[j];
        }
    }
    __syncthreads();

    uint32_t aP = smem_u32(pA);
    uint32_t wP = smem_u32(pW);
    int mhalf = wid & 1;
    int nq = wid >> 1;
    int gid = lane >> 2, lc = (lane & 3) * 2;

    float c[2][4][4];
    mma_stage(aP, wP, mhalf, nq, lane, c);
    __syncthreads();

    // ---- epilogue 1: relu(C+b1) -> fp16 into A plane ----
    #pragma unroll
    for (int mt = 0; mt < 2; mt++)
        #pragma unroll
        for (int nt = 0; nt < 4; nt++) {
            int col = nq * 32 + nt * 8 + lc;
            float2 bb = *(const float2*)&b1[col];
            int r0 = mhalf * 32 + mt * 16 + gid;
            float f0 = fmaxf(c[mt][nt][0] + bb.x, 0.f);
            float f1 = fmaxf(c[mt][nt][1] + bb.y, 0.f);
            float f2 = fmaxf(c[mt][nt][2] + bb.x, 0.f);
            float f3 = fmaxf(c[mt][nt][3] + bb.y, 0.f);
            store_h16(pA, r0,     col, f0, f1);
            store_h16(pA, r0 + 8, col, f2, f3);
        }

    // ---- stage W2 into the same W buffer (same barrier window) ----
    {
        const float4* sw = (const float4*)g_whi[widx + 1];
        float4* dW = (float4*)pW;
        #pragma unroll
        for (int i = 0; i < 8; i++) {
            int j = tid + 256 * i;
            dW[j] = sw[j];
        }
    }
    __syncthreads();

    mma_stage(aP, wP, mhalf, nq, lane, c);

    // ---- epilogue 2: C + b2 (+relu) -> fp16 gmem ----
    #pragma unroll
    for (int mt = 0; mt < 2; mt++)
        #pragma unroll
        for (int nt = 0; nt < 4; nt++) {
            int col = nq * 32 + nt * 8 + lc;
            float2 bb = *(const float2*)&b2[col];
            float v0 = c[mt][nt][0] + bb.x;
            float v1 = c[mt][nt][1] + bb.y;
            float v2 = c[mt][nt][2] + bb.x;
            float v3 = c[mt][nt][3] + bb.y;
            if (relu2) {
                v0 = fmaxf(v0, 0.f); v1 = fmaxf(v1, 0.f);
                v2 = fmaxf(v2, 0.f); v3 = fmaxf(v3, 0.f);
            }
            int r0 = mhalf * 32 + mt * 16 + gid;
            int n0 = nodeBase + r0;
            int n1 = n0 + 8;
            if (n0 < NN) stcsh2(&hout16[n0 * DD + col], v0, v1);
            if (n1 < NN) stcsh2(&hout16[n1 * DD + col], v2, v3);
        }
}

// ---------------- mean pool over sorted batch + cleanup ----------------------
__device__ __forceinline__ int lbound_batch(const void* b, int val, int is64) {
    int lo = 0, hi = NN;
    if (is64) {
        const long long* p = (const long long*)b;
        long long v = val;
        while (lo < hi) { int mid = (lo + hi) >> 1; if (p[mid] < v) lo = mid + 1; else hi = mid; }
    } else {
        const int* p = (const int*)b;
        while (lo < hi) { int mid = (lo + hi) >> 1; if (p[mid] < val) lo = mid + 1; else hi = mid; }
    }
    return lo;
}

__global__ void pool_kernel(const __half* __restrict__ h,
                            const void* __restrict__ batch,
                            const void* __restrict__ ei,
                            float* __restrict__ out) {
    // fused cleanup: restore invariants for the next kernel_launch call
    {
        int gtid = blockIdx.x * 512 + threadIdx.x;   // 65536 threads
        g_deg[gtid] = 0;
        int g2 = gtid + 65536;
        if (g2 < NN) g_deg[g2] = 0;
        if (gtid < NB) g_desc[gtid] = 0ULL;
    }
    __shared__ int s_is64;
    if (threadIdx.x == 0) s_is64 = detect64(ei);
    __syncthreads();
    int g = blockIdx.x;
    int d2 = threadIdx.x & 63;    // half2 column index (0..63)
    int sub = threadIdx.x >> 6;   // 0..7
    int start = lbound_batch(batch, g, s_is64);
    int end   = lbound_batch(batch, g + 1, s_is64);
    const __half2* h2 = (const __half2*)h;
    float2 acc = make_float2(0.f, 0.f);
    for (int n = start + sub; n < end; n += 8) {
        float2 v = __half22float2(h2[n * 64 + d2]);
        acc.x += v.x;
        acc.y += v.y;
    }
    __shared__ float2 red[512];
    red[threadIdx.x] = acc;
    __syncthreads();
    if (sub == 0) {
        float2 s = make_float2(0.f, 0.f);
        #pragma unroll
        for (int q = 0; q < 8; q++) {
            s.x += red[d2 + q * 64].x;
            s.y += red[d2 + q * 64].y;
        }
        int cnt = end - start;
        float inv = 1.f / (float)(cnt > 0 ? cnt : 1);
        out[g * DD + d2 * 2]     = s.x * inv;
        out[g * DD + d2 * 2 + 1] = s.y * inv;
    }
}

// ---------------- launch ------------------------------------------------------
extern "C" void kernel_launch(void* const* d_in, const int* in_sizes, int n_in,
                              void* d_out, int out_size) {
    const float* x = (const float*)d_in[0];
    const void* ei = d_in[1];
    const void* batch = d_in[2];
    const float *W1[3], *b1[3], *W2[3], *b2[3];
    for (int l = 0; l < 3; l++) {
        W1[l] = (const float*)d_in[3 + 4 * l];
        b1[l] = (const float*)d_in[4 + 4 * l];
        W2[l] = (const float*)d_in[5 + 4 * l];
        b2[l] = (const float*)d_in[6 + 4 * l];
    }
    float* out = (float*)d_out;

    cudaFuncSetAttribute(mma_kernel,
                         cudaFuncAttributeMaxDynamicSharedMemorySize, 49152);

    __half *xh, *hh0, *hh1;
    cudaGetSymbolAddress((void**)&xh, g_xh);
    cudaGetSymbolAddress((void**)&hh0, g_hh0);
    cudaGetSymbolAddress((void**)&hh1, g_hh1);

    const int agg_blocks = (NN * 32 + 255) / 256;   // 12500

    pre_kernel<<<6 + HISTB + XCONVB, 512>>>(ei, x, W1[0], W2[0], W1[1], W2[1],
                                            W1[2], W2[2]);                       // 0
    scan_kernel<<<NB, 512>>>();                                                   // 1
    fill_kernel<<<NE / 512, 512>>>(ei);                                           // 2

    agg_kernel<<<agg_blocks, 256>>>(xh);                                          // 3 (profiled)
    mma_kernel<<<TLCNT, 256, 49152>>>(b1[0], b2[0], hh0, 0, 1);                   // 4
    agg_kernel<<<agg_blocks, 256>>>(hh0);                                         // 5
    mma_kernel<<<TLCNT, 256, 49152>>>(b1[1], b2[1], hh1, 2, 1);                   // 6
    agg_kernel<<<agg_blocks, 256>>>(hh1);                                         // 7
    mma_kernel<<<TLCNT, 256, 49152>>>(b1[2], b2[2], hh0, 4, 0);                   // 8

    pool_kernel<<<NG, 512>>>(hh0, batch, ei, out);                                // 9
}